// round 1
// baseline (speedup 1.0000x reference)
#include <cuda_runtime.h>

// Problem constants
#define I_ 3
#define H_ 2048
#define O_ 2
#define R_ 2
#define S_ 4
#define G_ 7
#define B_ 32
#define T_ 512
#define ALPHA_ 0.2f
#define NSTD_ 0.05f

#define NTHREADS 512
#define NWARPS (NTHREADS / 32)
#define EPT 4  // elements per thread: 512*4 = 2048 = H

__device__ __forceinline__ float fast_tanh(float x) {
    // tanh(x) = 1 - 2/(1+exp(2x)); exact saturation at +-inf behavior
    float e = __expf(2.0f * x);
    return 1.0f - __fdividef(2.0f, 1.0f + e);
}

__device__ __forceinline__ float4 warp_reduce4(float4 p) {
#pragma unroll
    for (int off = 16; off; off >>= 1) {
        p.x += __shfl_xor_sync(0xffffffffu, p.x, off);
        p.y += __shfl_xor_sync(0xffffffffu, p.y, off);
        p.z += __shfl_xor_sync(0xffffffffu, p.z, off);
        p.w += __shfl_xor_sync(0xffffffffu, p.w, off);
    }
    return p;
}

// One barrier per call. part must alternate buffers between consecutive calls.
__device__ __forceinline__ float4 block_reduce4(float4 p, float4 (*part)[NWARPS],
                                                int buf, int warp, int lane) {
    p = warp_reduce4(p);
    if (lane == 0) part[buf][warp] = p;
    __syncthreads();
    float4 v = (lane < NWARPS) ? part[buf][lane] : make_float4(0.f, 0.f, 0.f, 0.f);
    v = warp_reduce4(v);   // butterfly over all 32 lanes; lanes >= NWARPS contribute 0
    return v;              // every lane holds the block total
}

__global__ __launch_bounds__(NTHREADS, 1)
void lowrank_rnn_kernel(const float* __restrict__ input,   // (B,T,I)
                        const float* __restrict__ noise,   // (B,T,H)
                        const float* __restrict__ wi,      // (I,S,G)
                        const float* __restrict__ unitwi,  // (I,S,1)
                        const float* __restrict__ m,       // (R,S,G)
                        const float* __restrict__ n,       // (R,S,G)
                        const float* __restrict__ unitm,   // (R,S,1)
                        const float* __restrict__ unitn,   // (R,S,1)
                        const float* __restrict__ wo,      // (O,S,G)
                        const float* __restrict__ h0,      // (S,G)
                        const float* __restrict__ unith0,  // (S,1)
                        const float* __restrict__ bias,    // (S,1)
                        const float* __restrict__ gb,      // (G,H)
                        const float* __restrict__ uv,      // (1,H)
                        const float* __restrict__ sup,     // (S,H)
                        float* __restrict__ out)           // out(B,T,O) ++ traj(B,T,H)
{
    const int b    = blockIdx.x;
    const int tid  = threadIdx.x;
    const int lane = tid & 31;
    const int warp = tid >> 5;

    __shared__ float4 s_part[2][NWARPS];

    // ------------------------------------------------------------------
    // Phase 1: build per-element effective weights in registers (one-time)
    // ------------------------------------------------------------------
    float hreg[EPT];
    float c_m0[EPT], c_m1[EPT], c_n0[EPT], c_n1[EPT];
    float c_wo0[EPT], c_wo1[EPT], c_bias[EPT];
    float c_wi0[EPT], c_wi1[EPT], c_wi2[EPT];

#pragma unroll
    for (int e = 0; e < EPT; e++) {
        const int hidx = tid * EPT + e;
        float gvec[G_];
#pragma unroll
        for (int g = 0; g < G_; g++) gvec[g] = gb[g * H_ + hidx];
        const float uvh = uv[hidx];

        float awi0 = 0.f, awi1 = 0.f, awi2 = 0.f;
        float am0 = 0.f, am1 = 0.f, an0 = 0.f, an1 = 0.f;
        float awo0 = 0.f, awo1 = 0.f, ah0 = 0.f, ab = 0.f;

#pragma unroll
        for (int s = 0; s < S_; s++) {
            const float su = sup[s * H_ + hidx];

            float d0 = 0.f, d1 = 0.f, d2 = 0.f;
#pragma unroll
            for (int g = 0; g < G_; g++) {
                d0 += wi[(0 * S_ + s) * G_ + g] * gvec[g];
                d1 += wi[(1 * S_ + s) * G_ + g] * gvec[g];
                d2 += wi[(2 * S_ + s) * G_ + g] * gvec[g];
            }
            awi0 += (d0 + unitwi[0 * S_ + s] * uvh) * su;
            awi1 += (d1 + unitwi[1 * S_ + s] * uvh) * su;
            awi2 += (d2 + unitwi[2 * S_ + s] * uvh) * su;

            float dm0 = 0.f, dm1 = 0.f, dn0 = 0.f, dn1 = 0.f;
#pragma unroll
            for (int g = 0; g < G_; g++) {
                dm0 += m[(0 * S_ + s) * G_ + g] * gvec[g];
                dm1 += m[(1 * S_ + s) * G_ + g] * gvec[g];
                dn0 += n[(0 * S_ + s) * G_ + g] * gvec[g];
                dn1 += n[(1 * S_ + s) * G_ + g] * gvec[g];
            }
            am0 += (dm0 + unitm[0 * S_ + s] * uvh) * su;
            am1 += (dm1 + unitm[1 * S_ + s] * uvh) * su;
            an0 += (dn0 + unitn[0 * S_ + s] * uvh) * su;
            an1 += (dn1 + unitn[1 * S_ + s] * uvh) * su;

            float do0 = 0.f, do1 = 0.f, dh = 0.f;
#pragma unroll
            for (int g = 0; g < G_; g++) {
                do0 += wo[(0 * S_ + s) * G_ + g] * gvec[g];
                do1 += wo[(1 * S_ + s) * G_ + g] * gvec[g];
                dh  += h0[s * G_ + g] * gvec[g];
            }
            awo0 += do0 * su;
            awo1 += do1 * su;
            ah0  += dh * su + unith0[s] * uvh * su;
            ab   += bias[s] * uvh * su;
        }
        hreg[e]  = ah0;
        c_m0[e]  = am0;  c_m1[e]  = am1;
        c_n0[e]  = an0;  c_n1[e]  = an1;
        c_wo0[e] = awo0; c_wo1[e] = awo1;
        c_bias[e] = ab;
        c_wi0[e] = awi0; c_wi1[e] = awi1; c_wi2[e] = awi2;
    }

    // ------------------------------------------------------------------
    // Phase 2: recurrence. One fused 4-channel block reduction per step:
    //   (r.n0, r.n1, r.wo0, r.wo1) where r = tanh(h_{t+1})
    // ------------------------------------------------------------------
    const float* zb = noise + (size_t)b * T_ * H_;
    const float* xb = input + (size_t)b * T_ * I_;
    float* outp  = out + (size_t)b * T_ * O_;
    float* trajp = out + (size_t)B_ * T_ * O_ + (size_t)b * T_ * H_;

    // Initial reduction: Sn from r0 = tanh(h0)
    {
        float4 p = make_float4(0.f, 0.f, 0.f, 0.f);
#pragma unroll
        for (int e = 0; e < EPT; e++) {
            float r = fast_tanh(hreg[e]);
            p.x += r * c_n0[e];
            p.y += r * c_n1[e];
        }
        p = block_reduce4(p, s_part, 0, warp, lane);
        // stash in p.x/p.y below via Sn
        s_part[1][0].x = 0.f;  // (no-op touch; keeps compiler honest about smem)
        __syncthreads();
        // carry
        hreg[0] = hreg[0];  // no-op
        // store Sn in registers:
        // (declared below)
        // we fall through with p held
        // NOTE: structured so Sn0/Sn1 initialized from p
        // ------------------------------------------------
        // declare outside the scope:
        // (handled below)
        // store into statics:
        // use variables:
        // (see Sn0/Sn1 declaration after this block)
        // we re-materialize via shared? simpler: write into s_part[1][1]
        if (tid == 0) s_part[1][1] = p;
        __syncthreads();
    }
    float4 S0 = s_part[1][1];
    float Sn0 = S0.x, Sn1 = S0.y;
    __syncthreads();

    // Prefetch noise / input two steps ahead
    float4 z0 = *(const float4*)(zb + 0 * (size_t)H_ + tid * 4);
    float4 z1 = *(const float4*)(zb + 1 * (size_t)H_ + tid * 4);
    float xA0 = xb[0], xA1 = xb[1], xA2 = xb[2];
    float xB0 = xb[3], xB1 = xb[4], xB2 = xb[5];

    for (int t = 0; t < T_; t++) {
        const int tp = (t + 2 < T_) ? (t + 2) : (T_ - 1);
        float4 z2 = *(const float4*)(zb + (size_t)tp * H_ + tid * 4);
        const float xC0 = xb[tp * I_ + 0];
        const float xC1 = xb[tp * I_ + 1];
        const float xC2 = xb[tp * I_ + 2];

        const float zarr[EPT] = {z0.x, z0.y, z0.z, z0.w};
        float4 pr = make_float4(0.f, 0.f, 0.f, 0.f);
        float hnew[EPT];
#pragma unroll
        for (int e = 0; e < EPT; e++) {
            float xw  = xA0 * c_wi0[e] + xA1 * c_wi1[e] + xA2 * c_wi2[e];
            float rec = Sn0 * c_m0[e] + Sn1 * c_m1[e];
            float h   = hreg[e];
            h = h + c_bias[e] + NSTD_ * zarr[e] + ALPHA_ * (rec + xw - h);
            hreg[e] = h;
            hnew[e] = h;
            float r = fast_tanh(h);
            pr.x += r * c_n0[e];
            pr.y += r * c_n1[e];
            pr.z += r * c_wo0[e];
            pr.w += r * c_wo1[e];
        }
        // stream traj
        *(float4*)(trajp + (size_t)t * H_ + tid * 4) =
            make_float4(hnew[0], hnew[1], hnew[2], hnew[3]);

        float4 Rv = block_reduce4(pr, s_part, t & 1, warp, lane);
        Sn0 = Rv.x;
        Sn1 = Rv.y;
        if (tid == 0) {
            outp[t * O_ + 0] = Rv.z;
            outp[t * O_ + 1] = Rv.w;
        }

        z0 = z1; z1 = z2;
        xA0 = xB0; xA1 = xB1; xA2 = xB2;
        xB0 = xC0; xB1 = xC1; xB2 = xC2;
    }
}

extern "C" void kernel_launch(void* const* d_in, const int* in_sizes, int n_in,
                              void* d_out, int out_size) {
    (void)in_sizes; (void)n_in; (void)out_size;
    const float* input    = (const float*)d_in[0];
    const float* noise    = (const float*)d_in[1];
    const float* wi       = (const float*)d_in[2];
    const float* unitwi   = (const float*)d_in[3];
    const float* m        = (const float*)d_in[4];
    const float* n        = (const float*)d_in[5];
    const float* unitm    = (const float*)d_in[6];
    const float* unitn    = (const float*)d_in[7];
    const float* wo       = (const float*)d_in[8];
    const float* h0       = (const float*)d_in[9];
    const float* unith0   = (const float*)d_in[10];
    const float* bias     = (const float*)d_in[11];
    const float* gb       = (const float*)d_in[12];
    const float* uv       = (const float*)d_in[13];
    const float* sup      = (const float*)d_in[14];
    float* out            = (float*)d_out;

    lowrank_rnn_kernel<<<B_, NTHREADS>>>(input, noise, wi, unitwi, m, n, unitm,
                                         unitn, wo, h0, unith0, bias, gb, uv,
                                         sup, out);
}